// round 11
// baseline (speedup 1.0000x reference)
#include <cuda_runtime.h>

// Inverse db4 wavelet reconstruction (polyphase, hardcoded taps, 2-tile pipeline).
// in : [B=16, L=16000, 128]  (first 64 ch = approx, last 64 = detail)
// out: [B=16, 2L=32000, 64]
//
//   out[2k]   = l1*a[k-1]+l3*a[k]+l5*a[k+1]+l7*a[k+2] + h1*d[k-1]+...
//   out[2k+1] = l0*a[k-1]+l2*a[k]+l4*a[k+1]+l6*a[k+2] + h0*d[k-1]+...
// x out of [0,L) is zero.
//
// Each thread processes TWO tiles; tile-B loads are issued before tile-A
// compute so every warp keeps ~14 LDG.128 outstanding through the compute
// phase (steady DRAM read demand instead of burst-then-drought).

#define BATCH 16
#define SEQ_L 16000
#define C_IN  128
#define C_OUT 64
#define KPT   4          // k positions per tile per thread
#define NW    (KPT + 3)  // rows in each load window (7)
#define TPB   128        // 16 c4-groups x 8 k-tiles

// db4 dec_lo
#define D0 (-0.010597401784997278f)
#define D1 ( 0.032883011666982945f)
#define D2 ( 0.030841381835986965f)
#define D3 (-0.18703481171888114f)
#define D4 (-0.02798376941698385f)
#define D5 ( 0.6308807679295904f)
#define D6 ( 0.7148465705525415f)
#define D7 ( 0.23037781330885523f)
// rec_lo[i] = dec_lo[7-i]
#define L0 D7
#define L1 D6
#define L2 D5
#define L3 D4
#define L4 D3
#define L5 D2
#define L6 D1
#define L7 D0
// rec_hi[i] = (-1)^i * dec_lo[i]
#define H0 ( D0)
#define H1 (-D1)
#define H2 ( D2)
#define H3 (-D3)
#define H4 ( D4)
#define H5 (-D5)
#define H6 ( D6)
#define H7 (-D7)

__device__ __forceinline__ float4 f4zero() { return make_float4(0.f, 0.f, 0.f, 0.f); }

__device__ __forceinline__ void f4fma(float s, const float4& a, float4& acc) {
    acc.x = fmaf(a.x, s, acc.x);
    acc.y = fmaf(a.y, s, acc.y);
    acc.z = fmaf(a.z, s, acc.z);
    acc.w = fmaf(a.w, s, acc.w);
}

__device__ __forceinline__ void load_window(const float* __restrict__ ap, int k0,
                                            float4* a, float4* d)
{
    if (k0 >= 1 && k0 + KPT + 2 <= SEQ_L) {
        const float* p = ap + (size_t)(k0 - 1) * C_IN;
#pragma unroll
        for (int i = 0; i < NW; ++i) {
            a[i] = __ldcs(reinterpret_cast<const float4*>(p + (size_t)i * C_IN));
            d[i] = __ldcs(reinterpret_cast<const float4*>(p + (size_t)i * C_IN + C_OUT));
        }
    } else {
#pragma unroll
        for (int i = 0; i < NW; ++i) {
            const int k = k0 - 1 + i;
            if ((unsigned)k < (unsigned)SEQ_L) {
                const float* p = ap + (size_t)k * C_IN;
                a[i] = __ldcs(reinterpret_cast<const float4*>(p));
                d[i] = __ldcs(reinterpret_cast<const float4*>(p + C_OUT));
            } else {
                a[i] = f4zero();
                d[i] = f4zero();
            }
        }
    }
}

__device__ __forceinline__ void compute_store(const float4* a, const float4* d,
                                              int k0, float* __restrict__ op)
{
#pragma unroll
    for (int i = 0; i < KPT; ++i) {
        const int k = k0 + i;

        float4 ev = f4zero();   // out[2k]
        f4fma(L1, a[i], ev); f4fma(L3, a[i + 1], ev); f4fma(L5, a[i + 2], ev); f4fma(L7, a[i + 3], ev);
        f4fma(H1, d[i], ev); f4fma(H3, d[i + 1], ev); f4fma(H5, d[i + 2], ev); f4fma(H7, d[i + 3], ev);

        float4 od = f4zero();   // out[2k+1]
        f4fma(L0, a[i], od); f4fma(L2, a[i + 1], od); f4fma(L4, a[i + 2], od); f4fma(L6, a[i + 3], od);
        f4fma(H0, d[i], od); f4fma(H2, d[i + 1], od); f4fma(H4, d[i + 2], od); f4fma(H6, d[i + 3], od);

        __stcs(reinterpret_cast<float4*>(op + (size_t)(2 * k) * C_OUT), ev);
        __stcs(reinterpret_cast<float4*>(op + (size_t)(2 * k + 1) * C_OUT), od);
    }
}

__global__ __launch_bounds__(TPB)
void idwt_db4_kernel(const float* __restrict__ in,
                     float* __restrict__ out)
{
    const int tid = threadIdx.x;
    const int c4  = tid & 15;          // channel group of 4 (0..15)
    const int lk  = tid >> 4;          // local k-tile (0..7)

    constexpr int KTILES_PER_BLOCK = TPB / 16;                     // 8
    constexpr int K_PER_HALF       = KPT * KTILES_PER_BLOCK;       // 32
    constexpr int K_PER_BLOCK      = 2 * K_PER_HALF;               // 64
    constexpr int BLOCKS_PER_BATCH = SEQ_L / K_PER_BLOCK;          // 250

    const int b    = blockIdx.x / BLOCKS_PER_BATCH;
    const int blk  = blockIdx.x % BLOCKS_PER_BATCH;
    const int base = blk * K_PER_BLOCK;
    const int k0a  = base + lk * KPT;
    const int k0b  = base + K_PER_HALF + lk * KPT;

    const float* ap = in + (size_t)b * SEQ_L * C_IN + c4 * 4;   // approx base
    float* op = out + (size_t)b * (2 * SEQ_L) * C_OUT + c4 * 4;

    float4 aA[NW], dA[NW], aB[NW], dB[NW];

    load_window(ap, k0a, aA, dA);   // tile A loads
    load_window(ap, k0b, aB, dB);   // tile B loads — stay in flight during A's compute

    compute_store(aA, dA, k0a, op);
    compute_store(aB, dB, k0b, op);
}

extern "C" void kernel_launch(void* const* d_in, const int* in_sizes, int n_in,
                              void* d_out, int out_size)
{
    const float* in = (const float*)d_in[0];
    float* out      = (float*)d_out;
    (void)in_sizes; (void)n_in; (void)out_size;

    constexpr int KTILES_PER_BLOCK = TPB / 16;                       // 8
    constexpr int K_PER_BLOCK      = 2 * KPT * KTILES_PER_BLOCK;     // 64
    constexpr int BLOCKS_PER_BATCH = SEQ_L / K_PER_BLOCK;            // 250
    const dim3 grid(BATCH * BLOCKS_PER_BATCH);                       // 4000 blocks

    idwt_db4_kernel<<<grid, TPB>>>(in, out);
}

// round 12
// speedup vs baseline: 1.0130x; 1.0130x over previous
#include <cuda_runtime.h>

// Inverse db4 wavelet reconstruction (polyphase, hardcoded taps, 2-tile pipeline).
// in : [B=16, L=16000, 128]  (first 64 ch = approx, last 64 = detail)
// out: [B=16, 2L=32000, 64]
//
//   out[2k]   = l1*a[k-1]+l3*a[k]+l5*a[k+1]+l7*a[k+2] + h1*d[k-1]+...
//   out[2k+1] = l0*a[k-1]+l2*a[k]+l4*a[k+1]+l6*a[k+2] + h0*d[k-1]+...
// x out of [0,L) is zero.
//
// Each thread processes TWO tiles; tile-B loads are issued before tile-A
// compute so every warp keeps ~14 LDG.128 outstanding through the compute
// phase (steady DRAM read demand instead of burst-then-drought).

#define BATCH 16
#define SEQ_L 16000
#define C_IN  128
#define C_OUT 64
#define KPT   4          // k positions per tile per thread
#define NW    (KPT + 3)  // rows in each load window (7)
#define TPB   128        // 16 c4-groups x 8 k-tiles

// db4 dec_lo
#define D0 (-0.010597401784997278f)
#define D1 ( 0.032883011666982945f)
#define D2 ( 0.030841381835986965f)
#define D3 (-0.18703481171888114f)
#define D4 (-0.02798376941698385f)
#define D5 ( 0.6308807679295904f)
#define D6 ( 0.7148465705525415f)
#define D7 ( 0.23037781330885523f)
// rec_lo[i] = dec_lo[7-i]
#define L0 D7
#define L1 D6
#define L2 D5
#define L3 D4
#define L4 D3
#define L5 D2
#define L6 D1
#define L7 D0
// rec_hi[i] = (-1)^i * dec_lo[i]
#define H0 ( D0)
#define H1 (-D1)
#define H2 ( D2)
#define H3 (-D3)
#define H4 ( D4)
#define H5 (-D5)
#define H6 ( D6)
#define H7 (-D7)

__device__ __forceinline__ float4 f4zero() { return make_float4(0.f, 0.f, 0.f, 0.f); }

__device__ __forceinline__ void f4fma(float s, const float4& a, float4& acc) {
    acc.x = fmaf(a.x, s, acc.x);
    acc.y = fmaf(a.y, s, acc.y);
    acc.z = fmaf(a.z, s, acc.z);
    acc.w = fmaf(a.w, s, acc.w);
}

__device__ __forceinline__ void load_window(const float* __restrict__ ap, int k0,
                                            float4* a, float4* d)
{
    if (k0 >= 1 && k0 + KPT + 2 <= SEQ_L) {
        const float* p = ap + (size_t)(k0 - 1) * C_IN;
#pragma unroll
        for (int i = 0; i < NW; ++i) {
            a[i] = __ldcs(reinterpret_cast<const float4*>(p + (size_t)i * C_IN));
            d[i] = __ldcs(reinterpret_cast<const float4*>(p + (size_t)i * C_IN + C_OUT));
        }
    } else {
#pragma unroll
        for (int i = 0; i < NW; ++i) {
            const int k = k0 - 1 + i;
            if ((unsigned)k < (unsigned)SEQ_L) {
                const float* p = ap + (size_t)k * C_IN;
                a[i] = __ldcs(reinterpret_cast<const float4*>(p));
                d[i] = __ldcs(reinterpret_cast<const float4*>(p + C_OUT));
            } else {
                a[i] = f4zero();
                d[i] = f4zero();
            }
        }
    }
}

__device__ __forceinline__ void compute_store(const float4* a, const float4* d,
                                              int k0, float* __restrict__ op)
{
#pragma unroll
    for (int i = 0; i < KPT; ++i) {
        const int k = k0 + i;

        float4 ev = f4zero();   // out[2k]
        f4fma(L1, a[i], ev); f4fma(L3, a[i + 1], ev); f4fma(L5, a[i + 2], ev); f4fma(L7, a[i + 3], ev);
        f4fma(H1, d[i], ev); f4fma(H3, d[i + 1], ev); f4fma(H5, d[i + 2], ev); f4fma(H7, d[i + 3], ev);

        float4 od = f4zero();   // out[2k+1]
        f4fma(L0, a[i], od); f4fma(L2, a[i + 1], od); f4fma(L4, a[i + 2], od); f4fma(L6, a[i + 3], od);
        f4fma(H0, d[i], od); f4fma(H2, d[i + 1], od); f4fma(H4, d[i + 2], od); f4fma(H6, d[i + 3], od);

        __stcs(reinterpret_cast<float4*>(op + (size_t)(2 * k) * C_OUT), ev);
        __stcs(reinterpret_cast<float4*>(op + (size_t)(2 * k + 1) * C_OUT), od);
    }
}

__global__ __launch_bounds__(TPB)
void idwt_db4_kernel(const float* __restrict__ in,
                     float* __restrict__ out)
{
    const int tid = threadIdx.x;
    const int c4  = tid & 15;          // channel group of 4 (0..15)
    const int lk  = tid >> 4;          // local k-tile (0..7)

    constexpr int KTILES_PER_BLOCK = TPB / 16;                     // 8
    constexpr int K_PER_HALF       = KPT * KTILES_PER_BLOCK;       // 32
    constexpr int K_PER_BLOCK      = 2 * K_PER_HALF;               // 64
    constexpr int BLOCKS_PER_BATCH = SEQ_L / K_PER_BLOCK;          // 250

    const int b    = blockIdx.x / BLOCKS_PER_BATCH;
    const int blk  = blockIdx.x % BLOCKS_PER_BATCH;
    const int base = blk * K_PER_BLOCK;
    const int k0a  = base + lk * KPT;
    const int k0b  = base + K_PER_HALF + lk * KPT;

    const float* ap = in + (size_t)b * SEQ_L * C_IN + c4 * 4;   // approx base
    float* op = out + (size_t)b * (2 * SEQ_L) * C_OUT + c4 * 4;

    float4 aA[NW], dA[NW], aB[NW], dB[NW];

    load_window(ap, k0a, aA, dA);   // tile A loads
    load_window(ap, k0b, aB, dB);   // tile B loads — stay in flight during A's compute

    compute_store(aA, dA, k0a, op);
    compute_store(aB, dB, k0b, op);
}

extern "C" void kernel_launch(void* const* d_in, const int* in_sizes, int n_in,
                              void* d_out, int out_size)
{
    const float* in = (const float*)d_in[0];
    float* out      = (float*)d_out;
    (void)in_sizes; (void)n_in; (void)out_size;

    constexpr int KTILES_PER_BLOCK = TPB / 16;                       // 8
    constexpr int K_PER_BLOCK      = 2 * KPT * KTILES_PER_BLOCK;     // 64
    constexpr int BLOCKS_PER_BATCH = SEQ_L / K_PER_BLOCK;            // 250
    const dim3 grid(BATCH * BLOCKS_PER_BATCH);                       // 4000 blocks

    idwt_db4_kernel<<<grid, TPB>>>(in, out);
}